// round 11
// baseline (speedup 1.0000x reference)
#include <cuda_runtime.h>
#include <stdint.h>

#define Bc 32
#define Sc 128
#define Hc 128
#define BSH (Bc * Sc * Hc)

__device__ float g_M[BSH];

// ---------------------------------------------------------------------------
__device__ __forceinline__ float gelu_f(float x) {
    return 0.5f * x * (1.0f + erff(x * 0.7071067811865476f));
}
__device__ __forceinline__ unsigned long long dup2(float x) {
    unsigned long long r; unsigned int u = __float_as_uint(x);
    asm("mov.b64 %0, {%1, %1};" : "=l"(r) : "r"(u)); return r;
}
__device__ __forceinline__ void fma2(unsigned long long &d, unsigned long long a,
                                     unsigned long long b) {
    asm("fma.rn.f32x2 %0, %1, %2, %3;" : "=l"(d) : "l"(a), "l"(b), "l"(d));
}
__device__ __forceinline__ float lo32(unsigned long long v) {
    return __uint_as_float((unsigned int)v);
}
__device__ __forceinline__ float hi32(unsigned long long v) {
    return __uint_as_float((unsigned int)(v >> 32));
}
__device__ __forceinline__ uint32_t s2u(const void* p) {
    uint32_t a;
    asm("{ .reg .u64 t; cvta.to.shared.u64 t, %1; cvt.u32.u64 %0, t; }" : "=r"(a) : "l"(p));
    return a;
}
__device__ __forceinline__ void cpasync16(uint32_t dst, const void* src) {
    asm volatile("cp.async.ca.shared.global [%0], [%1], 16;" :: "r"(dst), "l"(src));
}
#define CP_COMMIT() asm volatile("cp.async.commit_group;" ::: "memory")
#define CP_WAIT0()  asm volatile("cp.async.wait_group 0;" ::: "memory")
#define CP_WAIT1()  asm volatile("cp.async.wait_group 1;" ::: "memory")

// ---------------------------------------------------------------------------
// Mix kernel v4: class-batched, 3 CTAs/SM, small accumulator (8h x 4t).
// Class s = ceil((j+1)/16): 16 j's x 2s t-slabs (8 cols) per j -> 4s blocks.
// Warp w: slab_id = blk*8+w; j = 16(s-1)+slab_id/(2s); t0 = (slab_id%(2s))*8.
// Thread: hg = lane>>1 (8 h's, packed pairs from contiguous smem),
//         tg = lane&1  (4 t's, W dup'd in registers).
//   Y[h,t] = sum_k X[b,k,h] * W1[j,k,t]; out += gelu(Y+b1)*W2 (atomicAdd)
// Output pre-initialized to base + b2[j].
// ---------------------------------------------------------------------------
__global__ __launch_bounds__(256, 3) void mix_kernel(
    const float* __restrict__ X,     // [B,S,H]
    const float* __restrict__ W1,    // [S,S,S] (this scale)
    const float* __restrict__ b1,    // [S,S]
    const float* __restrict__ W2,    // [S,S]
    float* __restrict__ out)         // [B,S,H], pre-initialized
{
    __shared__ __align__(16) float Xs[2][16][128];     // 16 KB
    __shared__ __align__(16) float Ws[2][16][8][8];    //  8 KB

    const int bx = blockIdx.x;
    const int b  = bx & 31;
    const int cb = bx >> 5;          // 0..143, descending s
    int s, cbase;
    if      (cb < 32)  { s = 8; cbase = 0;   }
    else if (cb < 60)  { s = 7; cbase = 32;  }
    else if (cb < 84)  { s = 6; cbase = 60;  }
    else if (cb < 104) { s = 5; cbase = 84;  }
    else if (cb < 120) { s = 4; cbase = 104; }
    else if (cb < 132) { s = 3; cbase = 120; }
    else if (cb < 140) { s = 2; cbase = 132; }
    else               { s = 1; cbase = 140; }
    const int blk = cb - cbase;      // [0, 4s)

    const int tid  = threadIdx.x;
    const int w    = tid >> 5;
    const int lane = tid & 31;
    const int hg   = lane >> 1;      // 16 h-groups of 8
    const int tg   = lane & 1;       // 2 t-groups of 4
    const int h0   = hg * 8;

    const int slab_id = blk * 8 + w;
    const int jloc    = slab_id / (2 * s);
    const int tsl     = slab_id - jloc * (2 * s);
    const int j       = ((s - 1) << 4) + jloc;
    const int t0      = tsl * 8;

    const float* Xg = X + (long)b * Sc * Hc;
    const uint32_t xsb = s2u(Xs), wsb = s2u(Ws);

    unsigned long long acc[4][4];    // [h-pair][t]  = 32 regs
#pragma unroll
    for (int r = 0; r < 4; ++r)
#pragma unroll
        for (int c = 0; c < 4; ++c) acc[r][c] = 0ull;

    // ---- chunk issue: X 8KB (512x16B) + W 4KB (256x16B) ----
    auto issue = [&](int c, int buf) {
        const int k0 = c << 4;
#pragma unroll
        for (int p = 0; p < 2; ++p) {   // X
            int i = tid + p * 256;
            int row = i >> 5, c4 = (i & 31) * 4;
            cpasync16(xsb + (uint32_t)(buf * 2048 + row * 128 + c4) * 4,
                      Xg + (k0 + row) * 128 + c4);
        }
        {                               // W: one 16B line per thread
            int kk = tid >> 4, rem = tid & 15;
            int lw = rem >> 1, o4 = (rem & 1) * 4;
            int sid = blk * 8 + lw;
            int jl = sid / (2 * s);
            int jj = ((s - 1) << 4) + jl;
            int tt = (sid - jl * 2 * s) * 8;
            cpasync16(wsb + (uint32_t)((((buf * 16 + kk) * 8 + lw) * 8) + o4) * 4,
                      W1 + (long)jj * 16384 + (k0 + kk) * 128 + tt + o4);
        }
    };

    issue(0, 0);
    CP_COMMIT();
    if (s > 1) { issue(1, 1); CP_COMMIT(); }

    for (int c = 0; c < s; ++c) {
        if (c == s - 1) { CP_WAIT0(); } else { CP_WAIT1(); }
        __syncthreads();
        const int buf = c & 1;
#pragma unroll
        for (int kk = 0; kk < 16; ++kk) {
            ulonglong2 xa = *(const ulonglong2*)&Xs[buf][kk][h0];       // h pairs
            ulonglong2 xb = *(const ulonglong2*)&Xs[buf][kk][h0 + 4];
            float4 wf = *(const float4*)&Ws[buf][kk][w][tg * 4];
            unsigned long long w0 = dup2(wf.x), w1 = dup2(wf.y);
            unsigned long long w2 = dup2(wf.z), w3 = dup2(wf.w);
            fma2(acc[0][0], xa.x, w0); fma2(acc[0][1], xa.x, w1);
            fma2(acc[0][2], xa.x, w2); fma2(acc[0][3], xa.x, w3);
            fma2(acc[1][0], xa.y, w0); fma2(acc[1][1], xa.y, w1);
            fma2(acc[1][2], xa.y, w2); fma2(acc[1][3], xa.y, w3);
            fma2(acc[2][0], xb.x, w0); fma2(acc[2][1], xb.x, w1);
            fma2(acc[2][2], xb.x, w2); fma2(acc[2][3], xb.x, w3);
            fma2(acc[3][0], xb.y, w0); fma2(acc[3][1], xb.y, w1);
            fma2(acc[3][2], xb.y, w2); fma2(acc[3][3], xb.y, w3);
        }
        __syncthreads();
        if (c + 2 < s) { issue(c + 2, buf); }
        CP_COMMIT();
    }

    // ---- epilogue: gelu * W2, reduce over t, atomicAdd into out ----
    float part[8];
#pragma unroll
    for (int r = 0; r < 8; ++r) part[r] = 0.0f;
#pragma unroll
    for (int c = 0; c < 4; ++c) {
        int t = t0 + tg * 4 + c;
        float b1v = b1[j * Sc + t];   // zero for t > j
        float w2v = W2[j * Sc + t];   // zero for t > j
#pragma unroll
        for (int r = 0; r < 4; ++r) {
            unsigned long long v = acc[r][c];
            part[2 * r]     += gelu_f(lo32(v) + b1v) * w2v;
            part[2 * r + 1] += gelu_f(hi32(v) + b1v) * w2v;
        }
    }
#pragma unroll
    for (int r = 0; r < 8; ++r)
        part[r] += __shfl_xor_sync(0xffffffffu, part[r], 1);
    if (tg == 0) {
        float* o = out + ((long)b * Sc + j) * Hc + h0;
#pragma unroll
        for (int r = 0; r < 8; ++r) atomicAdd(o + r, part[r]);
    }
}

// ---------------------------------------------------------------------------
// init: out[b,j,h] = base[b,j,h] + b2[j]
// ---------------------------------------------------------------------------
__global__ void init_kernel(const float4* __restrict__ base,
                            const float* __restrict__ b2,
                            float4* __restrict__ out)
{
    int i = blockIdx.x * blockDim.x + threadIdx.x;
    if (i < BSH / 4) {
        int j = (i >> 5) & 127;
        float bv = b2[j];
        float4 v = base[i];
        v.x += bv; v.y += bv; v.z += bv; v.w += bv;
        out[i] = v;
    }
}

// ---------------------------------------------------------------------------
// Fused MLP v2 (R10 version — measured win): 512 threads, unrolled k-loops.
// ---------------------------------------------------------------------------
#define MRS 132
#define MLP_SMEM_BYTES ((2 * 32 * MRS + 2 * 128 * 128) * 4)

__global__ __launch_bounds__(512, 1) void mlp_fused(
    const float* __restrict__ in, const float* __restrict__ Wm1,
    const float* __restrict__ bm1, const float* __restrict__ Wm2,
    const float* __restrict__ bm2, float* __restrict__ out)
{
    extern __shared__ __align__(16) float sm[];
    float* A    = sm;                  // [32][MRS]
    float* Mid  = sm + 32 * MRS;       // [32][MRS]
    float* W1s  = sm + 2 * 32 * MRS;   // [128][128]
    float* W2s  = W1s + 128 * 128;     // [128][128]

    const int tid = threadIdx.x;
    const int r   = tid >> 4;
    const int cg  = tid & 15;
    const int c0  = cg * 8;
    const int r0g = blockIdx.x * 32;
    const uint32_t smb = s2u(sm);

    for (int i = tid; i < 32 * 32; i += 512) {
        int row = i >> 5, c4 = (i & 31) * 4;
        cpasync16(smb + (uint32_t)(row * MRS + c4) * 4,
                  in + (r0g + row) * 128 + c4);
    }
    for (int i = tid; i < 128 * 32; i += 512) {
        int row = i >> 5, c4 = (i & 31) * 4;
        cpasync16(smb + (uint32_t)(2 * 32 * MRS + row * 128 + c4) * 4,
                  Wm1 + row * 128 + c4);
    }
    CP_COMMIT();
    for (int i = tid; i < 128 * 32; i += 512) {
        int row = i >> 5, c4 = (i & 31) * 4;
        cpasync16(smb + (uint32_t)(2 * 32 * MRS + 128 * 128 + row * 128 + c4) * 4,
                  Wm2 + row * 128 + c4);
    }
    CP_COMMIT();

    CP_WAIT1();
    __syncthreads();

    unsigned long long acc[4];
#pragma unroll
    for (int c = 0; c < 4; ++c) acc[c] = 0ull;
    {
        const float* Ar = A + r * MRS;
#pragma unroll 8
        for (int k = 0; k < 128; ++k) {
            unsigned long long ad = dup2(Ar[k]);
            ulonglong2 w0 = *(const ulonglong2*)&W1s[k * 128 + c0];
            ulonglong2 w1 = *(const ulonglong2*)&W1s[k * 128 + c0 + 4];
            fma2(acc[0], ad, w0.x); fma2(acc[1], ad, w0.y);
            fma2(acc[2], ad, w1.x); fma2(acc[3], ad, w1.y);
        }
        float* Mr = Mid + r * MRS + c0;
#pragma unroll
        for (int c = 0; c < 8; ++c) {
            unsigned long long v = acc[c >> 1];
            float y = ((c & 1) ? hi32(v) : lo32(v)) + bm1[c0 + c];
            Mr[c] = gelu_f(y);
        }
    }
    CP_WAIT0();
    __syncthreads();

#pragma unroll
    for (int c = 0; c < 4; ++c) acc[c] = 0ull;
    {
        const float* Mr = Mid + r * MRS;
#pragma unroll 8
        for (int k = 0; k < 128; ++k) {
            unsigned long long ad = dup2(Mr[k]);
            ulonglong2 w0 = *(const ulonglong2*)&W2s[k * 128 + c0];
            ulonglong2 w1 = *(const ulonglong2*)&W2s[k * 128 + c0 + 4];
            fma2(acc[0], ad, w0.x); fma2(acc[1], ad, w0.y);
            fma2(acc[2], ad, w1.x); fma2(acc[3], ad, w1.y);
        }
        float o[8];
#pragma unroll
        for (int c = 0; c < 8; ++c) {
            unsigned long long v = acc[c >> 1];
            o[c] = ((c & 1) ? hi32(v) : lo32(v)) + bm2[c0 + c];
        }
        float* og = out + (r0g + r) * 128 + c0;
        *(float4*)&og[0] = make_float4(o[0], o[1], o[2], o[3]);
        *(float4*)&og[4] = make_float4(o[4], o[5], o[6], o[7]);
    }
}

// ---------------------------------------------------------------------------
__global__ void copy_kernel(const float4* __restrict__ src,
                            float4* __restrict__ dst, int n4)
{
    int i = blockIdx.x * blockDim.x + threadIdx.x;
    if (i < n4) dst[i] = src[i];
}

// ---------------------------------------------------------------------------
extern "C" void kernel_launch(void* const* d_in, const int* in_sizes, int n_in,
                              void* d_out, int out_size)
{
    const float* trend0 = (const float*)d_in[0];
    const float* trend1 = (const float*)d_in[1];
    const float* trend2 = (const float*)d_in[2];
    const float* W1     = (const float*)d_in[3];
    const float* b1     = (const float*)d_in[4];
    const float* W2     = (const float*)d_in[5];
    const float* b2     = (const float*)d_in[6];
    const float* Wm1    = (const float*)d_in[7];
    const float* bm1    = (const float*)d_in[8];
    const float* Wm2    = (const float*)d_in[9];
    const float* bm2    = (const float*)d_in[10];

    float* out = (float*)d_out;
    float* O0 = out;             // mlp(trend0 + res1)
    float* O1 = out + BSH;       // mlp(trend1 + res0)
    float* O2 = out + 2 * BSH;   // trend2

    float* pM;
    cudaGetSymbolAddress((void**)&pM, g_M);

    cudaFuncSetAttribute(mlp_fused, cudaFuncAttributeMaxDynamicSharedMemorySize,
                         MLP_SMEM_BYTES);

    dim3 blk(256);
    dim3 mixGrid(144 * Bc);      // 4608 blocks, descending class size
    dim3 initGrid(BSH / 4 / 256);

    // scale i=0: X = trend2, base = trend1 -> O1 = mlp(M0)
    init_kernel<<<initGrid, blk>>>((const float4*)trend1, b2, (float4*)pM);
    mix_kernel<<<mixGrid, blk>>>(trend2, W1, b1, W2, pM);
    mlp_fused<<<128, 512, MLP_SMEM_BYTES>>>(pM, Wm1, bm1, Wm2, bm2, O1);

    // scale i=1: X = O1, base = trend0 -> O0 = mlp(M1)
    init_kernel<<<initGrid, blk>>>((const float4*)trend0, b2 + Sc, (float4*)pM);
    mix_kernel<<<mixGrid, blk>>>(O1, W1 + Sc * Sc * Sc, b1 + Sc * Sc,
                                 W2 + Sc * Sc, pM);
    mlp_fused<<<128, 512, MLP_SMEM_BYTES>>>(pM, Wm1, bm1, Wm2, bm2, O0);

    // out2 = trend2
    copy_kernel<<<BSH / 4 / 256, 256>>>((const float4*)trend2, (float4*)O2,
                                        BSH / 4);
}

// round 12
// speedup vs baseline: 1.0958x; 1.0958x over previous
#include <cuda_runtime.h>
#include <stdint.h>

#define Bc 32
#define Sc 128
#define Hc 128
#define BSH (Bc * Sc * Hc)

__device__ float g_M[BSH];

// ---------------------------------------------------------------------------
__device__ __forceinline__ float gelu_f(float x) {
    return 0.5f * x * (1.0f + erff(x * 0.7071067811865476f));
}
__device__ __forceinline__ unsigned long long dup2(float x) {
    unsigned long long r; unsigned int u = __float_as_uint(x);
    asm("mov.b64 %0, {%1, %1};" : "=l"(r) : "r"(u)); return r;
}
__device__ __forceinline__ void fma2(unsigned long long &d, unsigned long long a,
                                     unsigned long long b) {
    asm("fma.rn.f32x2 %0, %1, %2, %3;" : "=l"(d) : "l"(a), "l"(b), "l"(d));
}
__device__ __forceinline__ float lo32(unsigned long long v) {
    return __uint_as_float((unsigned int)v);
}
__device__ __forceinline__ float hi32(unsigned long long v) {
    return __uint_as_float((unsigned int)(v >> 32));
}
__device__ __forceinline__ uint32_t s2u(const void* p) {
    uint32_t a;
    asm("{ .reg .u64 t; cvta.to.shared.u64 t, %1; cvt.u32.u64 %0, t; }" : "=r"(a) : "l"(p));
    return a;
}
__device__ __forceinline__ void cpasync16(uint32_t dst, const void* src) {
    asm volatile("cp.async.ca.shared.global [%0], [%1], 16;" :: "r"(dst), "l"(src));
}
#define CP_COMMIT() asm volatile("cp.async.commit_group;" ::: "memory")
#define CP_WAIT0()  asm volatile("cp.async.wait_group 0;" ::: "memory")
#define CP_WAIT1()  asm volatile("cp.async.wait_group 1;" ::: "memory")

// ---------------------------------------------------------------------------
// Mix kernel v5: R10 geometry (2 CTA/SM, warp = (j, 16-t slab), class-batched)
// but X staged resident ONCE and W double-buffered PER WARP via each warp's
// own cp.async group -> no __syncthreads in the K loop.
// Class s = ceil((j+1)/16): 16 j's x s slabs -> 2s blocks of 8 warps.
//   Y[h,t] = sum_k X[b,k,h] * W1[j,k,t]; out += gelu(Y+b1)*W2 (atomicAdd)
// Output pre-initialized to base + b2[j].
// ---------------------------------------------------------------------------
#define MIX_SMEM_BYTES (16384 * 4 + 4096 * 4)   // X 64KB + W 16KB

__global__ __launch_bounds__(256, 2) void mix_kernel(
    const float* __restrict__ X,     // [B,S,H]
    const float* __restrict__ W1,    // [S,S,S] (this scale)
    const float* __restrict__ b1,    // [S,S]
    const float* __restrict__ W2,    // [S,S]
    float* __restrict__ out)         // [B,S,H], pre-initialized
{
    extern __shared__ __align__(16) float sm[];
    float* Xall = sm;                // [16s][128] (<= 64KB)
    float* Wb   = sm + 16384;        // [2][8][16][16] = 16KB

    const int bx = blockIdx.x;
    const int b  = bx & 31;
    const int cb = bx >> 5;          // 0..71, descending s
    int s, cbase;
    if      (cb < 16) { s = 8; cbase = 0;  }
    else if (cb < 30) { s = 7; cbase = 16; }
    else if (cb < 42) { s = 6; cbase = 30; }
    else if (cb < 52) { s = 5; cbase = 42; }
    else if (cb < 60) { s = 4; cbase = 52; }
    else if (cb < 66) { s = 3; cbase = 60; }
    else if (cb < 70) { s = 2; cbase = 66; }
    else              { s = 1; cbase = 70; }
    const int blk8 = cb - cbase;     // [0, 2s)

    const int tid  = threadIdx.x;
    const int w    = tid >> 5;
    const int lane = tid & 31;
    const int hg   = lane >> 1;      // 16 h-groups of 8
    const int tg   = lane & 1;       // 2 t-groups of 8
    const int h0   = hg * 8;

    const int slab_id = blk8 * 8 + w;
    const int jloc    = slab_id / s;
    const int slabl   = slab_id - jloc * s;
    const int j       = ((s - 1) << 4) + jloc;
    const int t0      = slabl << 4;

    const float* Xg = X + (long)b * Sc * Hc;
    const float* Wg = W1 + (long)j * 16384 + t0;   // this warp's W slab
    const uint32_t xsb = s2u(Xall), wsb = s2u(Wb);

    unsigned long long acc[8][4];
#pragma unroll
    for (int r = 0; r < 8; ++r)
#pragma unroll
        for (int c = 0; c < 4; ++c) acc[r][c] = 0ull;

    // ---- per-warp W chunk issue: 16kk x 16t = 1KB = 64 x 16B lines ----
    auto issueW = [&](int c, int buf) {
        const int k0 = c << 4;
#pragma unroll
        for (int p = 0; p < 2; ++p) {
            int i = lane * 2 + p;            // 0..63
            int kk = i >> 2, o4 = (i & 3) * 4;
            cpasync16(wsb + (uint32_t)((((buf * 8 + w) * 16 + kk) * 16) + o4) * 4,
                      Wg + (k0 + kk) * 128 + o4);
        }
    };

    // ---- prologue: X (one group) + W0 + W1 ----
    {
        const int nx = 2 * s;                // float4 lines per thread
        for (int p = 0; p < nx; ++p) {
            int idx = tid + p * 256;
            int row = idx >> 5, c4 = (idx & 31) * 4;
            cpasync16(xsb + (uint32_t)(row * 128 + c4) * 4,
                      Xg + row * 128 + c4);
        }
        CP_COMMIT();
    }
    issueW(0, 0);
    CP_COMMIT();
    if (s > 1) { issueW(1, 1); CP_COMMIT(); }

    // ---- K loop: no block barriers ----
    for (int c = 0; c < s; ++c) {
        if (c == s - 1) { CP_WAIT0(); } else { CP_WAIT1(); }
        if (c == 0) { __syncthreads(); } else { __syncwarp(); }
        const int buf = c & 1;
        const float* Xc = Xall + (c * 16) * 128;
        const float* Wc = Wb + ((buf * 8 + w) * 16) * 16;
#pragma unroll
        for (int kk = 0; kk < 16; ++kk) {
            float4 x0 = *(const float4*)&Xc[kk * 128 + h0];
            float4 x1 = *(const float4*)&Xc[kk * 128 + h0 + 4];
            ulonglong2 w0 = *(const ulonglong2*)&Wc[kk * 16 + tg * 8];
            ulonglong2 w1 = *(const ulonglong2*)&Wc[kk * 16 + tg * 8 + 4];
            float xv[8] = {x0.x, x0.y, x0.z, x0.w, x1.x, x1.y, x1.z, x1.w};
#pragma unroll
            for (int r = 0; r < 8; ++r) {
                unsigned long long ad = dup2(xv[r]);
                fma2(acc[r][0], ad, w0.x);
                fma2(acc[r][1], ad, w0.y);
                fma2(acc[r][2], ad, w1.x);
                fma2(acc[r][3], ad, w1.y);
            }
        }
        if (c + 2 < s) { issueW(c + 2, buf); CP_COMMIT(); }
    }

    // ---- epilogue: gelu * W2, reduce over t, atomicAdd into out ----
    float part[8];
#pragma unroll
    for (int r = 0; r < 8; ++r) part[r] = 0.0f;
    const int tbase = t0 + tg * 8;
#pragma unroll
    for (int c = 0; c < 8; ++c) {
        int t = tbase + c;
        float b1v = b1[j * Sc + t];   // zero for t > j
        float w2v = W2[j * Sc + t];   // zero for t > j
#pragma unroll
        for (int r = 0; r < 8; ++r) {
            unsigned long long v = acc[r][c >> 1];
            float y = ((c & 1) ? hi32(v) : lo32(v)) + b1v;
            part[r] += gelu_f(y) * w2v;
        }
    }
#pragma unroll
    for (int r = 0; r < 8; ++r)
        part[r] += __shfl_xor_sync(0xffffffffu, part[r], 1);
    if (tg == 0) {
        float* o = out + ((long)b * Sc + j) * Hc + h0;
#pragma unroll
        for (int r = 0; r < 8; ++r) atomicAdd(o + r, part[r]);
    }
}

// ---------------------------------------------------------------------------
// init: out[b,j,h] = base[b,j,h] + b2[j]
// ---------------------------------------------------------------------------
__global__ void init_kernel(const float4* __restrict__ base,
                            const float* __restrict__ b2,
                            float4* __restrict__ out)
{
    int i = blockIdx.x * blockDim.x + threadIdx.x;
    if (i < BSH / 4) {
        int j = (i >> 5) & 127;
        float bv = b2[j];
        float4 v = base[i];
        v.x += bv; v.y += bv; v.z += bv; v.w += bv;
        out[i] = v;
    }
}

// ---------------------------------------------------------------------------
// Fused MLP v2 (R10 measured win): 512 threads, unrolled k-loops.
// ---------------------------------------------------------------------------
#define MRS 132
#define MLP_SMEM_BYTES ((2 * 32 * MRS + 2 * 128 * 128) * 4)

__global__ __launch_bounds__(512, 1) void mlp_fused(
    const float* __restrict__ in, const float* __restrict__ Wm1,
    const float* __restrict__ bm1, const float* __restrict__ Wm2,
    const float* __restrict__ bm2, float* __restrict__ out)
{
    extern __shared__ __align__(16) float sm[];
    float* A    = sm;                  // [32][MRS]
    float* Mid  = sm + 32 * MRS;       // [32][MRS]
    float* W1s  = sm + 2 * 32 * MRS;   // [128][128]
    float* W2s  = W1s + 128 * 128;     // [128][128]

    const int tid = threadIdx.x;
    const int r   = tid >> 4;
    const int cg  = tid & 15;
    const int c0  = cg * 8;
    const int r0g = blockIdx.x * 32;
    const uint32_t smb = s2u(sm);

    for (int i = tid; i < 32 * 32; i += 512) {
        int row = i >> 5, c4 = (i & 31) * 4;
        cpasync16(smb + (uint32_t)(row * MRS + c4) * 4,
                  in + (r0g + row) * 128 + c4);
    }
    for (int i = tid; i < 128 * 32; i += 512) {
        int row = i >> 5, c4 = (i & 31) * 4;
        cpasync16(smb + (uint32_t)(2 * 32 * MRS + row * 128 + c4) * 4,
                  Wm1 + row * 128 + c4);
    }
    CP_COMMIT();
    for (int i = tid; i < 128 * 32; i += 512) {
        int row = i >> 5, c4 = (i & 31) * 4;
        cpasync16(smb + (uint32_t)(2 * 32 * MRS + 128 * 128 + row * 128 + c4) * 4,
                  Wm2 + row * 128 + c4);
    }
    CP_COMMIT();

    CP_WAIT1();
    __syncthreads();

    unsigned long long acc[4];
#pragma unroll
    for (int c = 0; c < 4; ++c) acc[c] = 0ull;
    {
        const float* Ar = A + r * MRS;
#pragma unroll 8
        for (int k = 0; k < 128; ++k) {
            unsigned long long ad = dup2(Ar[k]);
            ulonglong2 w0 = *(const ulonglong2*)&W1s[k * 128 + c0];
            ulonglong2 w1 = *(const ulonglong2*)&W1s[k * 128 + c0 + 4];
            fma2(acc[0], ad, w0.x); fma2(acc[1], ad, w0.y);
            fma2(acc[2], ad, w1.x); fma2(acc[3], ad, w1.y);
        }
        float* Mr = Mid + r * MRS + c0;
#pragma unroll
        for (int c = 0; c < 8; ++c) {
            unsigned long long v = acc[c >> 1];
            float y = ((c & 1) ? hi32(v) : lo32(v)) + bm1[c0 + c];
            Mr[c] = gelu_f(y);
        }
    }
    CP_WAIT0();
    __syncthreads();

#pragma unroll
    for (int c = 0; c < 4; ++c) acc[c] = 0ull;
    {
        const float* Mr = Mid + r * MRS;
#pragma unroll 8
        for (int k = 0; k < 128; ++k) {
            unsigned long long ad = dup2(Mr[k]);
            ulonglong2 w0 = *(const ulonglong2*)&W2s[k * 128 + c0];
            ulonglong2 w1 = *(const ulonglong2*)&W2s[k * 128 + c0 + 4];
            fma2(acc[0], ad, w0.x); fma2(acc[1], ad, w0.y);
            fma2(acc[2], ad, w1.x); fma2(acc[3], ad, w1.y);
        }
        float o[8];
#pragma unroll
        for (int c = 0; c < 8; ++c) {
            unsigned long long v = acc[c >> 1];
            o[c] = ((c & 1) ? hi32(v) : lo32(v)) + bm2[c0 + c];
        }
        float* og = out + (r0g + r) * 128 + c0;
        *(float4*)&og[0] = make_float4(o[0], o[1], o[2], o[3]);
        *(float4*)&og[4] = make_float4(o[4], o[5], o[6], o[7]);
    }
}

// ---------------------------------------------------------------------------
__global__ void copy_kernel(const float4* __restrict__ src,
                            float4* __restrict__ dst, int n4)
{
    int i = blockIdx.x * blockDim.x + threadIdx.x;
    if (i < n4) dst[i] = src[i];
}

// ---------------------------------------------------------------------------
extern "C" void kernel_launch(void* const* d_in, const int* in_sizes, int n_in,
                              void* d_out, int out_size)
{
    const float* trend0 = (const float*)d_in[0];
    const float* trend1 = (const float*)d_in[1];
    const float* trend2 = (const float*)d_in[2];
    const float* W1     = (const float*)d_in[3];
    const float* b1     = (const float*)d_in[4];
    const float* W2     = (const float*)d_in[5];
    const float* b2     = (const float*)d_in[6];
    const float* Wm1    = (const float*)d_in[7];
    const float* bm1    = (const float*)d_in[8];
    const float* Wm2    = (const float*)d_in[9];
    const float* bm2    = (const float*)d_in[10];

    float* out = (float*)d_out;
    float* O0 = out;             // mlp(trend0 + res1)
    float* O1 = out + BSH;       // mlp(trend1 + res0)
    float* O2 = out + 2 * BSH;   // trend2

    float* pM;
    cudaGetSymbolAddress((void**)&pM, g_M);

    cudaFuncSetAttribute(mix_kernel, cudaFuncAttributeMaxDynamicSharedMemorySize,
                         MIX_SMEM_BYTES);
    cudaFuncSetAttribute(mlp_fused, cudaFuncAttributeMaxDynamicSharedMemorySize,
                         MLP_SMEM_BYTES);

    dim3 blk(256);
    dim3 mixGrid(72 * Bc);       // 2304 blocks, descending class size
    dim3 initGrid(BSH / 4 / 256);

    // scale i=0: X = trend2, base = trend1 -> O1 = mlp(M0)
    init_kernel<<<initGrid, blk>>>((const float4*)trend1, b2, (float4*)pM);
    mix_kernel<<<mixGrid, blk, MIX_SMEM_BYTES>>>(trend2, W1, b1, W2, pM);
    mlp_fused<<<128, 512, MLP_SMEM_BYTES>>>(pM, Wm1, bm1, Wm2, bm2, O1);

    // scale i=1: X = O1, base = trend0 -> O0 = mlp(M1)
    init_kernel<<<initGrid, blk>>>((const float4*)trend0, b2 + Sc, (float4*)pM);
    mix_kernel<<<mixGrid, blk, MIX_SMEM_BYTES>>>(O1, W1 + Sc * Sc * Sc,
                                                 b1 + Sc * Sc, W2 + Sc * Sc, pM);
    mlp_fused<<<128, 512, MLP_SMEM_BYTES>>>(pM, Wm1, bm1, Wm2, bm2, O0);

    // out2 = trend2
    copy_kernel<<<BSH / 4 / 256, 256>>>((const float4*)trend2, (float4*)O2,
                                        BSH / 4);
}